// round 17
// baseline (speedup 1.0000x reference)
#include <cuda_runtime.h>
#include <cuda_bf16.h>
#include <cstdint>

#define IN_DIM  4096
#define OUT_DIM 4096
#define MX      8192          /* B*S = 4*2048 */
#define KE      12288         /* 3 * IN_DIM (split-bf16 K expansion) */

// ---------------------------------------------------------------------------
// Static device scratch. A-side K' pattern: [hi | hi | lo]; B-side: [hi | lo | hi]
// => bf16 MMA over K'=3*IN computes hi*hi + hi*lo + lo*hi (fp32-class accuracy).
// ---------------------------------------------------------------------------
__device__ __nv_bfloat16 g_Xe[(size_t)MX      * KE];  // x expanded      (A side)
__device__ __nv_bfloat16 g_Ye[(size_t)OUT_DIM * KE];  // centroid gather (A side)
__device__ __nv_bfloat16 g_Pe[(size_t)IN_DIM  * KE];  // Pi^T expanded   (B side)
__device__ __nv_bfloat16 g_We[(size_t)OUT_DIM * KE];  // W expanded      (B side)

__device__ __forceinline__ void split_bf16(float v, __nv_bfloat16 &h, __nv_bfloat16 &l) {
    h = __float2bfloat16(v);
    l = __float2bfloat16(v - __bfloat162float(h));
}

// ---------------------------------------------------------------------------
// Prep kernels (HBM-bound, ~100-150us total)
// ---------------------------------------------------------------------------
__global__ void expand_x_kernel(const float* __restrict__ x) {
    int64_t idx = (int64_t)blockIdx.x * blockDim.x + threadIdx.x;
    if (idx >= (int64_t)MX * IN_DIM / 4) return;
    int64_t m  = idx / (IN_DIM / 4);
    int     k4 = (int)(idx % (IN_DIM / 4)) * 4;
    float4 v = reinterpret_cast<const float4*>(x)[idx];
    alignas(8) __nv_bfloat16 h[4];
    alignas(8) __nv_bfloat16 l[4];
    split_bf16(v.x, h[0], l[0]);
    split_bf16(v.y, h[1], l[1]);
    split_bf16(v.z, h[2], l[2]);
    split_bf16(v.w, h[3], l[3]);
    __nv_bfloat16* dst = g_Xe + m * KE + k4;
    *reinterpret_cast<uint2*>(dst)              = *reinterpret_cast<const uint2*>(h);
    *reinterpret_cast<uint2*>(dst + IN_DIM)     = *reinterpret_cast<const uint2*>(h);
    *reinterpret_cast<uint2*>(dst + 2 * IN_DIM) = *reinterpret_cast<const uint2*>(l);
}

__global__ void expand_y_kernel(const int* __restrict__ idxs,
                                const float* __restrict__ cent) {
    int64_t idx = (int64_t)blockIdx.x * blockDim.x + threadIdx.x;
    if (idx >= (int64_t)OUT_DIM * IN_DIM / 4) return;
    int64_t o  = idx / (IN_DIM / 4);
    int     k4 = (int)(idx % (IN_DIM / 4)) * 4;
    int4 id = reinterpret_cast<const int4*>(idxs)[idx];
    alignas(8) __nv_bfloat16 h[4];
    alignas(8) __nv_bfloat16 l[4];
    split_bf16(__ldg(cent + id.x), h[0], l[0]);
    split_bf16(__ldg(cent + id.y), h[1], l[1]);
    split_bf16(__ldg(cent + id.z), h[2], l[2]);
    split_bf16(__ldg(cent + id.w), h[3], l[3]);
    __nv_bfloat16* dst = g_Ye + o * KE + k4;
    *reinterpret_cast<uint2*>(dst)              = *reinterpret_cast<const uint2*>(h);
    *reinterpret_cast<uint2*>(dst + IN_DIM)     = *reinterpret_cast<const uint2*>(h);
    *reinterpret_cast<uint2*>(dst + 2 * IN_DIM) = *reinterpret_cast<const uint2*>(l);
}

__global__ void expand_pi_kernel(const float* __restrict__ Pi) {
    __shared__ float tile[32][33];
    int bx = blockIdx.x, by = blockIdx.y;
    int tx = threadIdx.x, ty = threadIdx.y; // 32 x 8
#pragma unroll
    for (int s = 0; s < 4; s++) {
        int i = by * 32 + ty + s * 8;
        tile[ty + s * 8][tx] = Pi[(int64_t)i * IN_DIM + bx * 32 + tx];
    }
    __syncthreads();
#pragma unroll
    for (int s = 0; s < 4; s++) {
        int j = bx * 32 + ty + s * 8;
        int i = by * 32 + tx;
        float v = tile[tx][ty + s * 8];
        __nv_bfloat16 h, l;
        split_bf16(v, h, l);
        __nv_bfloat16* row = g_Pe + (int64_t)j * KE;
        row[i]              = h;
        row[IN_DIM + i]     = l;
        row[2 * IN_DIM + i] = h;
    }
}

// ---------------------------------------------------------------------------
// bf16 TN GEMM on the legacy mma.sync path (portable sm_103 ISA).
// C[m,n] = sum_k A[m,k]*B[n,k], K=KE.
// CTA tile 256x128x32, 512 threads (16 warps, 4x4), warp tile 64x32.
// 3-stage cp.async ring; ldmatrix.x4 fragment loads (conflict-free with the
// 16B-chunk XOR swizzle); mma.m16n8k16 bf16->fp32.
// EPI==1: C *= row_norms[m], re-split into g_We (B-side pattern)
// EPI==0: C += bias[n], write fp32 out
// ---------------------------------------------------------------------------
constexpr int BM = 256, BN = 128, BK = 32, NST = 3;
constexpr int NT_TILES = KE / BK;                   // 384
constexpr int A_ELEMS  = BM * BK;                   // 8192 bf16
constexpr int B_ELEMS  = BN * BK;                   // 4096 bf16
constexpr int STG_BYTES = (A_ELEMS + B_ELEMS) * 2;  // 24 KB / stage
constexpr int SMEM_ALLOC = NST * STG_BYTES;         // 72 KB

// element offset of (row r, col c) within a [rows x 32] bf16 tile,
// 16B chunks XOR-swizzled by (r>>1)&3  ->  conflict-free STS.128 and ldmatrix
__device__ __forceinline__ int swoff(int r, int c) {
    return (r << 5) + ((((c >> 3) ^ (r >> 1)) & 3) << 3) + (c & 7);
}

#define LDSM4(r0, r1, r2, r3, a)                                              \
    asm volatile("ldmatrix.sync.aligned.m8n8.x4.shared.b16 {%0,%1,%2,%3}, [%4];" \
                 : "=r"(r0), "=r"(r1), "=r"(r2), "=r"(r3) : "r"(a))

__device__ __forceinline__ void mma16816(float* c, const uint32_t* a, const uint32_t* b) {
    asm volatile(
        "mma.sync.aligned.m16n8k16.row.col.f32.bf16.bf16.f32 "
        "{%0,%1,%2,%3}, {%4,%5,%6,%7}, {%8,%9}, {%0,%1,%2,%3};\n"
        : "+f"(c[0]), "+f"(c[1]), "+f"(c[2]), "+f"(c[3])
        : "r"(a[0]), "r"(a[1]), "r"(a[2]), "r"(a[3]), "r"(b[0]), "r"(b[1]));
}

template <int EPI>
__global__ __launch_bounds__(512, 1)
void gemm_kernel(const float* __restrict__ vec, float* __restrict__ outF) {
    const __nv_bfloat16* __restrict__ A = (EPI == 1) ? g_Ye : g_Xe;
    const __nv_bfloat16* __restrict__ B = (EPI == 1) ? g_Pe : g_We;

    extern __shared__ __nv_bfloat16 smem[];
    const uint32_t sbase = (uint32_t)__cvta_generic_to_shared(smem);

    const int tid  = threadIdx.x;
    const int lane = tid & 31;
    const int warp = tid >> 5;
    const int wm   = (warp >> 2) * 64;   // 4 warp-rows -> 256
    const int wn   = (warp & 3) * 32;    // 4 warp-cols -> 128
    const int g    = lane >> 2;
    const int tig  = lane & 3;

    const int m0 = blockIdx.y * BM;
    const int n0 = blockIdx.x * BN;

    // ---- cp.async loader mapping: 16B chunks, 4 chunks per 32-col row ----
    // A: 1024 chunks (2 per thread), B: 512 chunks (1 per thread)
    const __nv_bfloat16* gaP[2];
    uint32_t saOff[2];
#pragma unroll
    for (int i = 0; i < 2; i++) {
        int c = tid + i * 512;
        int r = c >> 2, ch = c & 3;
        gaP[i]   = A + (size_t)(m0 + r) * KE + ch * 8;
        saOff[i] = (uint32_t)((r * 32 + ((ch ^ (r >> 1)) & 3) * 8) * 2);
    }
    const __nv_bfloat16* gbP;
    uint32_t sbOff;
    {
        int r = tid >> 2, ch = tid & 3;
        gbP   = B + (size_t)(n0 + r) * KE + ch * 8;
        sbOff = (uint32_t)((A_ELEMS + r * 32 + ((ch ^ (r >> 1)) & 3) * 8) * 2);
    }

    auto load_tile = [&](int kt, int sp) {
        const uint32_t so = sbase + sp * STG_BYTES;
        const int64_t  ko = (int64_t)kt * BK;
        asm volatile("cp.async.cg.shared.global [%0], [%1], 16;" :: "r"(so + saOff[0]), "l"(gaP[0] + ko));
        asm volatile("cp.async.cg.shared.global [%0], [%1], 16;" :: "r"(so + saOff[1]), "l"(gaP[1] + ko));
        asm volatile("cp.async.cg.shared.global [%0], [%1], 16;" :: "r"(so + sbOff),    "l"(gbP    + ko));
        asm volatile("cp.async.commit_group;" ::: "memory");
    };

    // ---- ldmatrix address precompute (byte offsets within a stage) ----
    // A x4 for (mt, ks): lanes 0-15 -> rows m..m+15 @ k_lo; 16-31 -> same rows @ k_lo+8
    uint32_t aOff[4][2];
#pragma unroll
    for (int mt = 0; mt < 4; mt++)
#pragma unroll
        for (int ks = 0; ks < 2; ks++) {
            int r = wm + mt * 16 + (lane & 15);
            int c = ks * 16 + ((lane >> 4) << 3);
            aOff[mt][ks] = (uint32_t)(swoff(r, c) * 2);
        }
    // B x4 for nt: lanes l -> row n+(l&7), col ((l>>3)<<3): k 0,8,16,24
    uint32_t bOff[4];
#pragma unroll
    for (int nt = 0; nt < 4; nt++) {
        int r = wn + nt * 8 + (lane & 7);
        int c = (lane >> 3) << 3;
        bOff[nt] = (uint32_t)((A_ELEMS + swoff(r, c)) * 2);
    }

    float acc[4][4][4];
#pragma unroll
    for (int i = 0; i < 4; i++)
#pragma unroll
        for (int j = 0; j < 4; j++)
#pragma unroll
            for (int q = 0; q < 4; q++) acc[i][j][q] = 0.f;

    load_tile(0, 0);
    load_tile(1, 1);

    for (int kt = 0; kt < NT_TILES; kt++) {
        const int s = kt % NST;
        if (kt + 2 < NT_TILES) {
            load_tile(kt + 2, (kt + 2) % NST);
            asm volatile("cp.async.wait_group 2;" ::: "memory");
        } else {
            asm volatile("cp.async.wait_group 0;" ::: "memory");
        }
        __syncthreads();

        const uint32_t st = sbase + s * STG_BYTES;

        // B fragments for both k16-steps: one x4 per nt
        uint32_t bf[4][4];
#pragma unroll
        for (int nt = 0; nt < 4; nt++)
            LDSM4(bf[nt][0], bf[nt][1], bf[nt][2], bf[nt][3], st + bOff[nt]);

#pragma unroll
        for (int ks = 0; ks < 2; ks++) {
#pragma unroll
            for (int mt = 0; mt < 4; mt++) {
                uint32_t af[4];
                LDSM4(af[0], af[1], af[2], af[3], st + aOff[mt][ks]);
#pragma unroll
                for (int nt = 0; nt < 4; nt++)
                    mma16816(acc[mt][nt], af, &bf[nt][ks * 2]);
            }
        }
        __syncthreads();
    }

    // ---- Epilogue ----
#pragma unroll
    for (int mt = 0; mt < 4; mt++) {
        const int row = m0 + wm + mt * 16 + g;
#pragma unroll
        for (int nt = 0; nt < 4; nt++) {
            const int col = n0 + wn + nt * 8 + 2 * tig;
            const float* c = acc[mt][nt];
            if (EPI == 0) {
                const float b0 = vec[col], b1 = vec[col + 1];
                float* o0 = outF + (int64_t)row * OUT_DIM + col;
                float* o1 = outF + (int64_t)(row + 8) * OUT_DIM + col;
                o0[0] = c[0] + b0;
                o0[1] = c[1] + b1;
                o1[0] = c[2] + b0;
                o1[1] = c[3] + b1;
            } else {
                const float r0 = vec[row], r1 = vec[row + 8];
                __nv_bfloat16* w0 = g_We + (int64_t)row * KE + col;
                __nv_bfloat16* w1 = g_We + (int64_t)(row + 8) * KE + col;
                __nv_bfloat16 h, l;
                float w;
                w = c[0] * r0; split_bf16(w, h, l); w0[0] = h; w0[IN_DIM]     = l; w0[2 * IN_DIM]     = h;
                w = c[1] * r0; split_bf16(w, h, l); w0[1] = h; w0[IN_DIM + 1] = l; w0[2 * IN_DIM + 1] = h;
                w = c[2] * r1; split_bf16(w, h, l); w1[0] = h; w1[IN_DIM]     = l; w1[2 * IN_DIM]     = h;
                w = c[3] * r1; split_bf16(w, h, l); w1[1] = h; w1[IN_DIM + 1] = l; w1[2 * IN_DIM + 1] = h;
            }
        }
    }
}

// ---------------------------------------------------------------------------
// Launch: prep -> GEMM1 (W = rn * (Yhat@Pi), re-split) -> GEMM2 (x@W^T + b)
// ---------------------------------------------------------------------------
extern "C" void kernel_launch(void* const* d_in, const int* in_sizes, int n_in,
                              void* d_out, int out_size) {
    const float* x         = (const float*)d_in[0];
    const int*   indices   = (const int*)  d_in[1];
    const float* centroids = (const float*)d_in[2];
    const float* Pi        = (const float*)d_in[3];
    const float* row_norms = (const float*)d_in[4];
    const float* bias      = (const float*)d_in[5];
    float*       out       = (float*)d_out;
    (void)in_sizes; (void)n_in; (void)out_size;

    static int smem_set = 0;
    if (!smem_set) {
        cudaFuncSetAttribute(gemm_kernel<0>, cudaFuncAttributeMaxDynamicSharedMemorySize, SMEM_ALLOC);
        cudaFuncSetAttribute(gemm_kernel<1>, cudaFuncAttributeMaxDynamicSharedMemorySize, SMEM_ALLOC);
        smem_set = 1;
    }

    {
        int64_t tot = (int64_t)MX * IN_DIM / 4;
        expand_x_kernel<<<(unsigned)((tot + 255) / 256), 256>>>(x);
    }
    {
        int64_t tot = (int64_t)OUT_DIM * IN_DIM / 4;
        expand_y_kernel<<<(unsigned)((tot + 255) / 256), 256>>>(indices, centroids);
    }
    {
        dim3 grid(IN_DIM / 32, IN_DIM / 32), blk(32, 8);
        expand_pi_kernel<<<grid, blk>>>(Pi);
    }
    {   // GEMM1: W[o,j] = rn[o] * (Yhat @ Pi)[o,j]; M=OUT_DIM, N=IN_DIM
        dim3 grid(IN_DIM / BN, OUT_DIM / BM);
        gemm_kernel<1><<<grid, 512, SMEM_ALLOC>>>(row_norms, nullptr);
    }
    {   // GEMM2: out[m,o] = x @ W^T + bias; M=MX, N=OUT_DIM
        dim3 grid(OUT_DIM / BN, MX / BM);
        gemm_kernel<0><<<grid, 512, SMEM_ALLOC>>>(bias, out);
    }
}